// round 9
// baseline (speedup 1.0000x reference)
#include <cuda_runtime.h>
#include <cuda_fp16.h>
#include <cstdint>

// ---------------- problem constants ----------------
#define N_ROWS 16384
#define KC 8192
#define D 256
#define LOSS_OFF 4194304
#define IDX_OFF 4194305

typedef unsigned long long u64;

// ---------------- device scratch ----------------
__device__ __half g_Ah[(size_t)N_ROWS * D];   // x fp16 [m][k]
__device__ __half g_Bh[(size_t)KC * D];       // e fp16 [n][k]
__device__ float g_Axf[(size_t)N_ROWS * D];   // x fp32 row-major (exact recheck)
__device__ float g_en2[KC];                   // ||e||^2 fp32
__device__ float g_xn2[N_ROWS];               // ||x||^2 per row
__device__ int g_maxen = 0;                   // max ||e||^2 bits (atomicMax, idempotent)
__device__ u64 g_part[(size_t)N_ROWS * 128];  // per row: 64 tiles x top-2
__device__ int g_idx[N_ROWS];
__device__ int g_queue[N_ROWS];               // rows needing exact recheck
__device__ int g_qn;                          // queue count (reset each launch in prepE)

// ---------------- helpers ----------------
__device__ __forceinline__ uint32_t smem_u32(const void* p) {
    uint32_t a;
    asm("{ .reg .u64 t; cvta.to.shared.u64 t, %1; cvt.u32.u64 %0, t; }" : "=r"(a) : "l"(p));
    return a;
}
__device__ __forceinline__ u64 packdi(float d, int idx) {
    uint32_t u = __float_as_uint(d);
    u = (u & 0x80000000u) ? ~u : (u | 0x80000000u);
    return ((u64)u << 32) | (uint32_t)idx;
}
__device__ __forceinline__ float unpackd(u64 p) {
    uint32_t u = (uint32_t)(p >> 32);
    u = (u & 0x80000000u) ? (u ^ 0x80000000u) : ~u;
    return __uint_as_float(u);
}
__device__ __forceinline__ void cpasync16(uint32_t sdst, const void* gsrc) {
    asm volatile("cp.async.cg.shared.global [%0], [%1], 16;" :: "r"(sdst), "l"(gsrc));
}
__device__ __forceinline__ void ldmx4(uint32_t addr, uint32_t& r0, uint32_t& r1,
                                      uint32_t& r2, uint32_t& r3) {
    asm volatile("ldmatrix.sync.aligned.m8n8.x4.shared.b16 {%0,%1,%2,%3}, [%4];"
                 : "=r"(r0), "=r"(r1), "=r"(r2), "=r"(r3) : "r"(addr));
}
__device__ __forceinline__ void mma16816(float* c, const uint32_t* a, const uint32_t* b) {
    asm volatile(
        "mma.sync.aligned.m16n8k16.row.col.f32.f16.f16.f32 "
        "{%0,%1,%2,%3}, {%4,%5,%6,%7}, {%8,%9}, {%0,%1,%2,%3};"
        : "+f"(c[0]), "+f"(c[1]), "+f"(c[2]), "+f"(c[3])
        : "r"(a[0]), "r"(a[1]), "r"(a[2]), "r"(a[3]), "r"(b[0]), "r"(b[1]));
}

// ---------------- prepE: E -> fp16 + ||e||^2 + max norm + inits --------------------
__global__ void prepE_kernel(const float* __restrict__ E, float* out) {
    int k = blockIdx.x * 8 + (threadIdx.x >> 5);
    int lane = threadIdx.x & 31;
    if (blockIdx.x == 0 && threadIdx.x == 0) { out[LOSS_OFF] = 0.0f; g_qn = 0; }
    const float4* p = (const float4*)(E + (size_t)k * D);
    float4 v0 = p[lane * 2], v1 = p[lane * 2 + 1];
    __half2 h0 = __floats2half2_rn(v0.x, v0.y), h1 = __floats2half2_rn(v0.z, v0.w);
    __half2 h2 = __floats2half2_rn(v1.x, v1.y), h3 = __floats2half2_rn(v1.z, v1.w);
    uint4 o;
    o.x = *(uint32_t*)&h0; o.y = *(uint32_t*)&h1;
    o.z = *(uint32_t*)&h2; o.w = *(uint32_t*)&h3;
    *(uint4*)(g_Bh + (size_t)k * D + lane * 8) = o;
    float s = v0.x*v0.x + v0.y*v0.y + v0.z*v0.z + v0.w*v0.w
            + v1.x*v1.x + v1.y*v1.y + v1.z*v1.z + v1.w*v1.w;
    #pragma unroll
    for (int off = 16; off > 0; off >>= 1) s += __shfl_xor_sync(0xffffffffu, s, off);
    if (lane == 0) {
        g_en2[k] = s;
        atomicMax(&g_maxen, __float_as_int(s));
    }
}

// ---------------- prepA: hs -> g_Ah fp16 + g_Axf fp32 (transposed), row norms ------
__global__ void prepA_kernel(const float* __restrict__ hs) {
    __shared__ float tile[32][33];
    __shared__ float snorm[8][32];
    int m0 = blockIdx.x * 32, b = m0 >> 10, p0 = m0 & 1023;
    int tx = threadIdx.x, ty = threadIdx.y;   // 32 x 8
    float nacc = 0.0f;
    for (int cc = 0; cc < 8; cc++) {
        int c0 = cc * 32;
        __syncthreads();
        #pragma unroll
        for (int i = 0; i < 4; i++) {
            int c = c0 + ty + i * 8;
            float v = hs[((size_t)(b * 256 + c)) * 1024 + p0 + tx];
            tile[ty + i * 8][tx] = v;
            nacc = fmaf(v, v, nacc);
        }
        __syncthreads();
        #pragma unroll
        for (int i = 0; i < 4; i++) {
            int row = ty + i * 8;
            float v = tile[tx][row];
            g_Ah[(size_t)(m0 + row) * D + c0 + tx] = __float2half_rn(v);
            g_Axf[(size_t)(m0 + row) * D + c0 + tx] = v;
        }
    }
    snorm[ty][tx] = nacc;
    __syncthreads();
    if (ty == 0) {
        float tot = 0.0f;
        #pragma unroll
        for (int j = 0; j < 8; j++) tot += snorm[j][tx];
        g_xn2[m0 + tx] = tot;
    }
}

// ---------------- main GEMM (fp16 mma.sync), CTA 128x128, 2-stage ------------------
#define SA_OFF(b) ((b) * 16384)
#define SB_OFF(b) (32768 + (b) * 16384)
#define SEN_OFF   65536
#define SPART_OFF 66048
#define SMEM_SZ   (1024 + 66048 + 4096)

__global__ void __launch_bounds__(256, 2)
gemm_kernel() {
    extern __shared__ char smem_raw[];
    char* base = (char*)(((uintptr_t)smem_raw + 1023) & ~(uintptr_t)1023);
    uint32_t sb = smem_u32(base);
    float* sEn = (float*)(base + SEN_OFF);
    u64* sPart = (u64*)(base + SPART_OFF);

    const int tid = threadIdx.x;
    const int lane = tid & 31, wid = tid >> 5;
    const int wm = wid & 3, wn = wid >> 2;
    const int ntile = blockIdx.x, mtile = blockIdx.y;
    const int m0 = mtile * 128, n0 = ntile * 128;

    if (tid < 128) sEn[tid] = g_en2[n0 + tid];

    auto load_chunk = [&](int c, int bf) {
        #pragma unroll
        for (int it = 0; it < 4; it++) {
            int idx = tid + it * 256;
            int row = idx >> 3, kg = idx & 7;
            uint32_t soff = row * 128 + (((uint32_t)(kg ^ (row & 7))) << 4);
            cpasync16(sb + SA_OFF(bf) + soff,
                      g_Ah + (size_t)(m0 + row) * D + c * 64 + kg * 8);
            cpasync16(sb + SB_OFF(bf) + soff,
                      g_Bh + (size_t)(n0 + row) * D + c * 64 + kg * 8);
        }
        asm volatile("cp.async.commit_group;");
    };

    float acc[2][8][4];
    #pragma unroll
    for (int mt = 0; mt < 2; mt++)
        #pragma unroll
        for (int nt = 0; nt < 8; nt++)
            #pragma unroll
            for (int q = 0; q < 4; q++) acc[mt][nt][q] = 0.0f;

    load_chunk(0, 0);

    for (int c = 0; c < 4; c++) {
        if (c + 1 < 4) {
            load_chunk(c + 1, (c + 1) & 1);
            asm volatile("cp.async.wait_group 1;" ::: "memory");
        } else {
            asm volatile("cp.async.wait_group 0;" ::: "memory");
        }
        __syncthreads();
        uint32_t ab = sb + SA_OFF(c & 1), bbse = sb + SB_OFF(c & 1);
        #pragma unroll
        for (int ks = 0; ks < 4; ks++) {
            uint32_t a[2][4], bb[8][2];
            uint32_t kg = ks * 2 + (lane >> 4);
            uint32_t kx = ((kg ^ (lane & 7)) << 4);
            #pragma unroll
            for (int mt = 0; mt < 2; mt++) {
                uint32_t row = wm * 32 + mt * 16 + (lane & 15);
                ldmx4(ab + row * 128 + kx, a[mt][0], a[mt][1], a[mt][2], a[mt][3]);
            }
            #pragma unroll
            for (int nt2 = 0; nt2 < 4; nt2++) {
                uint32_t row = wn * 64 + nt2 * 16 + (lane & 15);
                uint32_t r0, r1, r2, r3;
                ldmx4(bbse + row * 128 + kx, r0, r1, r2, r3);
                bb[nt2 * 2][0] = r0; bb[nt2 * 2][1] = r2;
                bb[nt2 * 2 + 1][0] = r1; bb[nt2 * 2 + 1][1] = r3;
            }
            #pragma unroll
            for (int mt = 0; mt < 2; mt++)
                #pragma unroll
                for (int nt = 0; nt < 8; nt++)
                    mma16816(acc[mt][nt], a[mt], bb[nt]);
        }
        __syncthreads();
    }

    // epilogue: per-row top-2 of dist = en2 - 2*dot within this 128-col tile
    #pragma unroll
    for (int mt = 0; mt < 2; mt++) {
        #pragma unroll
        for (int half = 0; half < 2; half++) {
            u64 t1 = ~0ull, t2 = ~0ull;
            #pragma unroll
            for (int nt = 0; nt < 8; nt++) {
                #pragma unroll
                for (int cc = 0; cc < 2; cc++) {
                    int col = wn * 64 + nt * 8 + (lane & 3) * 2 + cc;
                    float dist = fmaf(-2.0f, acc[mt][nt][half * 2 + cc], sEn[col]);
                    u64 pk = packdi(dist, n0 + col);
                    if (pk < t1) { t2 = t1; t1 = pk; }
                    else if (pk < t2) { t2 = pk; }
                }
            }
            #pragma unroll
            for (int dlt = 1; dlt <= 2; dlt <<= 1) {
                u64 o1 = __shfl_xor_sync(0xffffffffu, t1, dlt);
                u64 o2 = __shfl_xor_sync(0xffffffffu, t2, dlt);
                u64 n1 = min(t1, o1);
                u64 n2 = min(max(t1, o1), min(t2, o2));
                t1 = n1; t2 = n2;
            }
            if ((lane & 3) == 0) {
                int rl = wm * 32 + mt * 16 + half * 8 + (lane >> 2);
                sPart[rl * 4 + wn * 2] = t1;
                sPart[rl * 4 + wn * 2 + 1] = t2;
            }
        }
    }
    __syncthreads();
    if (tid < 128) {
        u64 a1 = sPart[tid * 4], a2 = sPart[tid * 4 + 1];
        u64 b1 = sPart[tid * 4 + 2], b2 = sPart[tid * 4 + 3];
        u64 n1 = min(a1, b1);
        u64 n2 = min(max(a1, b1), min(a2, b2));
        g_part[(size_t)(m0 + tid) * 128 + ntile * 2] = n1;
        g_part[(size_t)(m0 + tid) * 128 + ntile * 2 + 1] = n2;
    }
}

// ---------------- merge_fast: warp/row, fast path or enqueue ------------------------
__global__ void merge_fast_kernel(float* __restrict__ out) {
    int wid = threadIdx.x >> 5, lane = threadIdx.x & 31;
    int row = blockIdx.x * 8 + wid;

    const ulonglong2* pp = (const ulonglong2*)(g_part + (size_t)row * 128);
    ulonglong2 ea = pp[lane * 2], eb = pp[lane * 2 + 1];

    u64 m = min(min(ea.x, ea.y), min(eb.x, eb.y));
    #pragma unroll
    for (int o = 16; o > 0; o >>= 1) m = min(m, __shfl_xor_sync(0xffffffffu, m, o));

    float pad = 0.00196f * sqrtf(__ldg(&g_xn2[row]) * __int_as_float(g_maxen)) + 0.05f;
    float thr = unpackd(m) + pad;

    // ea = tile 2*lane (top1, top2), eb = tile 2*lane+1
    bool full = (unpackd(ea.y) <= thr) | (unpackd(eb.y) <= thr);
    int nc = (unpackd(ea.x) <= thr) + (unpackd(eb.x) <= thr);
    unsigned mf = __ballot_sync(0xffffffffu, full);
    #pragma unroll
    for (int o = 16; o > 0; o >>= 1) nc += __shfl_xor_sync(0xffffffffu, nc, o);

    if (lane == 0) {
        if (mf == 0 && nc == 1) {
            int k = (int)(m & 0xFFFFFFFFu);
            g_idx[row] = k;
            out[IDX_OFF + row] = (float)k;
        } else {
            int q = atomicAdd(&g_qn, 1);
            g_queue[q] = row;
        }
    }
}

// ---------------- merge_slow: block/row over queue, thread/code rechecks ------------
__global__ void __launch_bounds__(256, 4)
merge_slow_kernel(const float* __restrict__ E, float* __restrict__ out) {
    __shared__ u64 spart[128];
    __shared__ float sx[256];
    __shared__ u64 sred[8];
    __shared__ int scand[96];
    __shared__ int sfull[64];
    __shared__ int scnt[2];        // [0]=ncand, [1]=nfull
    __shared__ u64 sbest;

    int tid = threadIdx.x, lane = tid & 31, wid = tid >> 5;
    int nq = g_qn;

    for (int q = blockIdx.x; q < nq; q += gridDim.x) {
        int row = g_queue[q];
        if (tid < 128) spart[tid] = g_part[(size_t)row * 128 + tid];
        sx[tid] = __ldg(g_Axf + (size_t)row * D + tid);
        if (tid < 2) scnt[tid] = 0;
        if (tid == 0) sbest = ~0ull;
        __syncthreads();

        // block min over 128 entries
        u64 m = (tid < 128) ? spart[tid] : ~0ull;
        #pragma unroll
        for (int o = 16; o > 0; o >>= 1) m = min(m, __shfl_xor_sync(0xffffffffu, m, o));
        if (lane == 0) sred[wid] = m;
        __syncthreads();
        if (tid == 0) {
            u64 mm = ~0ull;
            #pragma unroll
            for (int w = 0; w < 4; w++) mm = min(mm, sred[w]);
            sred[0] = mm;
        }
        __syncthreads();
        float pad = 0.00196f * sqrtf(__ldg(&g_xn2[row]) * __int_as_float(g_maxen)) + 0.05f;
        float thr = unpackd(sred[0]) + pad;

        // classify tiles
        if (tid < 64) {
            u64 t1 = spart[tid * 2], t2 = spart[tid * 2 + 1];
            if (unpackd(t2) <= thr) {
                sfull[atomicAdd(&scnt[1], 1)] = tid;
            } else if (unpackd(t1) <= thr) {
                scand[atomicAdd(&scnt[0], 1)] = (int)(t1 & 0xFFFFFFFFu);
            }
        }
        __syncthreads();
        int ncand = scnt[0], nfull = scnt[1];

        const float4* sx4 = (const float4*)sx;
        u64 lbest = ~0ull;

        // total tasks: ncand singles + nfull*128 codes; one thread per code
        int ntask = ncand + nfull * 128;
        for (int t = tid; t < ntask; t += 256) {
            int k;
            if (t < ncand) k = scand[t];
            else {
                int ft = t - ncand;
                k = sfull[ft >> 7] * 128 + (ft & 127);
            }
            const float4* ek = (const float4*)(E + (size_t)k * D);
            float a0 = 0.f, a1 = 0.f, a2 = 0.f, a3 = 0.f;
            #pragma unroll
            for (int j = 0; j < 64; j += 4) {
                float4 e0 = __ldg(ek + j),     e1 = __ldg(ek + j + 1);
                float4 e2 = __ldg(ek + j + 2), e3 = __ldg(ek + j + 3);
                float4 x0 = sx4[j],     x1 = sx4[j + 1];
                float4 x2 = sx4[j + 2], x3 = sx4[j + 3];
                a0 = fmaf(x0.x, e0.x, fmaf(x0.y, e0.y, fmaf(x0.z, e0.z, fmaf(x0.w, e0.w, a0))));
                a1 = fmaf(x1.x, e1.x, fmaf(x1.y, e1.y, fmaf(x1.z, e1.z, fmaf(x1.w, e1.w, a1))));
                a2 = fmaf(x2.x, e2.x, fmaf(x2.y, e2.y, fmaf(x2.z, e2.z, fmaf(x2.w, e2.w, a2))));
                a3 = fmaf(x3.x, e3.x, fmaf(x3.y, e3.y, fmaf(x3.z, e3.z, fmaf(x3.w, e3.w, a3))));
            }
            float dot = (a0 + a1) + (a2 + a3);
            float dist = fmaf(-2.0f, dot, __ldg(&g_en2[k]));
            lbest = min(lbest, packdi(dist, k));
        }
        // warp reduce then shared atomic
        #pragma unroll
        for (int o = 16; o > 0; o >>= 1)
            lbest = min(lbest, __shfl_xor_sync(0xffffffffu, lbest, o));
        if (lane == 0 && lbest != ~0ull) atomicMin(&sbest, lbest);
        __syncthreads();
        if (tid == 0) {
            int k = (int)(sbest & 0xFFFFFFFFu);
            g_idx[row] = k;
            out[IDX_OFF + row] = (float)k;
        }
        __syncthreads();
    }
}

// ---------------- final gather + loss (float4) --------------------------------------
__global__ void final_kernel(const float* __restrict__ hs,
                             const float* __restrict__ E,
                             float* __restrict__ out) {
    __shared__ int sIdx[128];
    __shared__ float sRed[8];
    int tid = threadIdx.x;
    int lane = tid & 31;
    int row0 = blockIdx.x * 128;
    int b = row0 >> 10, p0 = row0 & 1023;
    size_t xbase = (size_t)b * 256 * 1024 + p0;

    if (tid < 128) sIdx[tid] = g_idx[row0 + tid];
    __syncthreads();

    int k0 = sIdx[lane * 4], k1 = sIdx[lane * 4 + 1];
    int k2 = sIdx[lane * 4 + 2], k3 = sIdx[lane * 4 + 3];

    float lsum = 0.0f;
    #pragma unroll 4
    for (int i = 0; i < 32; i++) {
        int c = i * 8 + (tid >> 5);
        size_t ad = xbase + (size_t)c * 1024 + lane * 4;
        float4 xv = *(const float4*)(hs + ad);
        float4 ev;
        ev.x = __ldg(E + (size_t)k0 * D + c);
        ev.y = __ldg(E + (size_t)k1 * D + c);
        ev.z = __ldg(E + (size_t)k2 * D + c);
        ev.w = __ldg(E + (size_t)k3 * D + c);
        *(float4*)(out + ad) = ev;
        float d0 = ev.x - xv.x, d1 = ev.y - xv.y;
        float d2 = ev.z - xv.z, d3 = ev.w - xv.w;
        lsum = fmaf(d0, d0, lsum);
        lsum = fmaf(d1, d1, lsum);
        lsum = fmaf(d2, d2, lsum);
        lsum = fmaf(d3, d3, lsum);
    }
    #pragma unroll
    for (int o = 16; o > 0; o >>= 1) lsum += __shfl_xor_sync(0xffffffffu, lsum, o);
    if ((tid & 31) == 0) sRed[tid >> 5] = lsum;
    __syncthreads();
    if (tid == 0) {
        float tot = 0.0f;
        #pragma unroll
        for (int w = 0; w < 8; w++) tot += sRed[w];
        atomicAdd(out + LOSS_OFF, tot * (1.25f / 4194304.0f));
    }
}

extern "C" void kernel_launch(void* const* d_in, const int* in_sizes, int n_in,
                              void* d_out, int out_size) {
    const float* hs = (const float*)d_in[0];
    const float* E  = (const float*)d_in[1];
    float* out = (float*)d_out;

    cudaFuncSetAttribute(gemm_kernel,
                         cudaFuncAttributeMaxDynamicSharedMemorySize, SMEM_SZ);

    prepE_kernel<<<KC / 8, 256>>>(E, out);
    prepA_kernel<<<N_ROWS / 32, dim3(32, 8)>>>(hs);
    gemm_kernel<<<dim3(KC / 128, N_ROWS / 128), 256, SMEM_SZ>>>();
    merge_fast_kernel<<<N_ROWS / 8, 256>>>(out);
    merge_slow_kernel<<<192, 256>>>(E, out);
    final_kernel<<<N_ROWS / 128, 256>>>(hs, E, out);
}

// round 10
// speedup vs baseline: 1.0764x; 1.0764x over previous
#include <cuda_runtime.h>
#include <cuda_fp16.h>
#include <cstdint>

// ---------------- problem constants ----------------
#define N_ROWS 16384
#define KC 8192
#define D 256
#define LOSS_OFF 4194304
#define IDX_OFF 4194305
#define QCAP (1 << 20)

typedef unsigned long long u64;

// ---------------- device scratch ----------------
__device__ __half g_Ah[(size_t)N_ROWS * D];   // x fp16 [m][k]
__device__ __half g_Bh[(size_t)KC * D];       // e fp16 [n][k]
__device__ float g_Axf[(size_t)N_ROWS * D];   // x fp32 row-major (exact recheck)
__device__ float g_en2[KC];                   // ||e||^2 fp32
__device__ float g_xn2[N_ROWS];               // ||x||^2 per row
__device__ int g_maxen = 0;                   // max ||e||^2 bits (atomicMax, idempotent)
__device__ u64 g_part[(size_t)N_ROWS * 128];  // per row: 64 tiles x top-2
__device__ int g_idx[N_ROWS];
__device__ u64 g_best[N_ROWS];                // packed best for queued rows
__device__ int g_queue[QCAP];                 // candidate tasks: (row<<13)|k
__device__ int g_rowq[N_ROWS];                // queued rows
__device__ int g_qn;                          // task count
__device__ int g_rqn;                         // row count

// ---------------- helpers ----------------
__device__ __forceinline__ uint32_t smem_u32(const void* p) {
    uint32_t a;
    asm("{ .reg .u64 t; cvta.to.shared.u64 t, %1; cvt.u32.u64 %0, t; }" : "=r"(a) : "l"(p));
    return a;
}
__device__ __forceinline__ u64 packdi(float d, int idx) {
    uint32_t u = __float_as_uint(d);
    u = (u & 0x80000000u) ? ~u : (u | 0x80000000u);
    return ((u64)u << 32) | (uint32_t)idx;
}
__device__ __forceinline__ float unpackd(u64 p) {
    uint32_t u = (uint32_t)(p >> 32);
    u = (u & 0x80000000u) ? (u ^ 0x80000000u) : ~u;
    return __uint_as_float(u);
}
__device__ __forceinline__ void cpasync16(uint32_t sdst, const void* gsrc) {
    asm volatile("cp.async.cg.shared.global [%0], [%1], 16;" :: "r"(sdst), "l"(gsrc));
}
__device__ __forceinline__ void ldmx4(uint32_t addr, uint32_t& r0, uint32_t& r1,
                                      uint32_t& r2, uint32_t& r3) {
    asm volatile("ldmatrix.sync.aligned.m8n8.x4.shared.b16 {%0,%1,%2,%3}, [%4];"
                 : "=r"(r0), "=r"(r1), "=r"(r2), "=r"(r3) : "r"(addr));
}
__device__ __forceinline__ void mma16816(float* c, const uint32_t* a, const uint32_t* b) {
    asm volatile(
        "mma.sync.aligned.m16n8k16.row.col.f32.f16.f16.f32 "
        "{%0,%1,%2,%3}, {%4,%5,%6,%7}, {%8,%9}, {%0,%1,%2,%3};"
        : "+f"(c[0]), "+f"(c[1]), "+f"(c[2]), "+f"(c[3])
        : "r"(a[0]), "r"(a[1]), "r"(a[2]), "r"(a[3]), "r"(b[0]), "r"(b[1]));
}

// ---------------- prepE: E -> fp16 + ||e||^2 + max norm + inits --------------------
__global__ void prepE_kernel(const float* __restrict__ E, float* out) {
    int k = blockIdx.x * 8 + (threadIdx.x >> 5);
    int lane = threadIdx.x & 31;
    if (blockIdx.x == 0 && threadIdx.x == 0) { out[LOSS_OFF] = 0.0f; g_qn = 0; g_rqn = 0; }
    const float4* p = (const float4*)(E + (size_t)k * D);
    float4 v0 = p[lane * 2], v1 = p[lane * 2 + 1];
    __half2 h0 = __floats2half2_rn(v0.x, v0.y), h1 = __floats2half2_rn(v0.z, v0.w);
    __half2 h2 = __floats2half2_rn(v1.x, v1.y), h3 = __floats2half2_rn(v1.z, v1.w);
    uint4 o;
    o.x = *(uint32_t*)&h0; o.y = *(uint32_t*)&h1;
    o.z = *(uint32_t*)&h2; o.w = *(uint32_t*)&h3;
    *(uint4*)(g_Bh + (size_t)k * D + lane * 8) = o;
    float s = v0.x*v0.x + v0.y*v0.y + v0.z*v0.z + v0.w*v0.w
            + v1.x*v1.x + v1.y*v1.y + v1.z*v1.z + v1.w*v1.w;
    #pragma unroll
    for (int off = 16; off > 0; off >>= 1) s += __shfl_xor_sync(0xffffffffu, s, off);
    if (lane == 0) {
        g_en2[k] = s;
        atomicMax(&g_maxen, __float_as_int(s));
    }
}

// ---------------- prepA: hs -> g_Ah fp16 + g_Axf fp32 (transposed), row norms ------
__global__ void prepA_kernel(const float* __restrict__ hs) {
    __shared__ float tile[32][33];
    __shared__ float snorm[8][32];
    int m0 = blockIdx.x * 32, b = m0 >> 10, p0 = m0 & 1023;
    int tx = threadIdx.x, ty = threadIdx.y;   // 32 x 8
    float nacc = 0.0f;
    for (int cc = 0; cc < 8; cc++) {
        int c0 = cc * 32;
        __syncthreads();
        #pragma unroll
        for (int i = 0; i < 4; i++) {
            int c = c0 + ty + i * 8;
            float v = hs[((size_t)(b * 256 + c)) * 1024 + p0 + tx];
            tile[ty + i * 8][tx] = v;
            nacc = fmaf(v, v, nacc);
        }
        __syncthreads();
        #pragma unroll
        for (int i = 0; i < 4; i++) {
            int row = ty + i * 8;
            float v = tile[tx][row];
            g_Ah[(size_t)(m0 + row) * D + c0 + tx] = __float2half_rn(v);
            g_Axf[(size_t)(m0 + row) * D + c0 + tx] = v;
        }
    }
    snorm[ty][tx] = nacc;
    __syncthreads();
    if (ty == 0) {
        float tot = 0.0f;
        #pragma unroll
        for (int j = 0; j < 8; j++) tot += snorm[j][tx];
        g_xn2[m0 + tx] = tot;
    }
}

// ---------------- main GEMM (fp16 mma.sync), CTA 128x128, 2-stage ------------------
#define SA_OFF(b) ((b) * 16384)
#define SB_OFF(b) (32768 + (b) * 16384)
#define SEN_OFF   65536
#define SPART_OFF 66048
#define SMEM_SZ   (1024 + 66048 + 4096)

__global__ void __launch_bounds__(256, 2)
gemm_kernel() {
    extern __shared__ char smem_raw[];
    char* base = (char*)(((uintptr_t)smem_raw + 1023) & ~(uintptr_t)1023);
    uint32_t sb = smem_u32(base);
    float* sEn = (float*)(base + SEN_OFF);
    u64* sPart = (u64*)(base + SPART_OFF);

    const int tid = threadIdx.x;
    const int lane = tid & 31, wid = tid >> 5;
    const int wm = wid & 3, wn = wid >> 2;
    const int ntile = blockIdx.x, mtile = blockIdx.y;
    const int m0 = mtile * 128, n0 = ntile * 128;

    if (tid < 128) sEn[tid] = g_en2[n0 + tid];

    auto load_chunk = [&](int c, int bf) {
        #pragma unroll
        for (int it = 0; it < 4; it++) {
            int idx = tid + it * 256;
            int row = idx >> 3, kg = idx & 7;
            uint32_t soff = row * 128 + (((uint32_t)(kg ^ (row & 7))) << 4);
            cpasync16(sb + SA_OFF(bf) + soff,
                      g_Ah + (size_t)(m0 + row) * D + c * 64 + kg * 8);
            cpasync16(sb + SB_OFF(bf) + soff,
                      g_Bh + (size_t)(n0 + row) * D + c * 64 + kg * 8);
        }
        asm volatile("cp.async.commit_group;");
    };

    float acc[2][8][4];
    #pragma unroll
    for (int mt = 0; mt < 2; mt++)
        #pragma unroll
        for (int nt = 0; nt < 8; nt++)
            #pragma unroll
            for (int q = 0; q < 4; q++) acc[mt][nt][q] = 0.0f;

    load_chunk(0, 0);

    for (int c = 0; c < 4; c++) {
        if (c + 1 < 4) {
            load_chunk(c + 1, (c + 1) & 1);
            asm volatile("cp.async.wait_group 1;" ::: "memory");
        } else {
            asm volatile("cp.async.wait_group 0;" ::: "memory");
        }
        __syncthreads();
        uint32_t ab = sb + SA_OFF(c & 1), bbse = sb + SB_OFF(c & 1);
        #pragma unroll
        for (int ks = 0; ks < 4; ks++) {
            uint32_t a[2][4], bb[8][2];
            uint32_t kg = ks * 2 + (lane >> 4);
            uint32_t kx = ((kg ^ (lane & 7)) << 4);
            #pragma unroll
            for (int mt = 0; mt < 2; mt++) {
                uint32_t row = wm * 32 + mt * 16 + (lane & 15);
                ldmx4(ab + row * 128 + kx, a[mt][0], a[mt][1], a[mt][2], a[mt][3]);
            }
            #pragma unroll
            for (int nt2 = 0; nt2 < 4; nt2++) {
                uint32_t row = wn * 64 + nt2 * 16 + (lane & 15);
                uint32_t r0, r1, r2, r3;
                ldmx4(bbse + row * 128 + kx, r0, r1, r2, r3);
                bb[nt2 * 2][0] = r0; bb[nt2 * 2][1] = r2;
                bb[nt2 * 2 + 1][0] = r1; bb[nt2 * 2 + 1][1] = r3;
            }
            #pragma unroll
            for (int mt = 0; mt < 2; mt++)
                #pragma unroll
                for (int nt = 0; nt < 8; nt++)
                    mma16816(acc[mt][nt], a[mt], bb[nt]);
        }
        __syncthreads();
    }

    // epilogue: per-row top-2 of dist = en2 - 2*dot within this 128-col tile
    #pragma unroll
    for (int mt = 0; mt < 2; mt++) {
        #pragma unroll
        for (int half = 0; half < 2; half++) {
            u64 t1 = ~0ull, t2 = ~0ull;
            #pragma unroll
            for (int nt = 0; nt < 8; nt++) {
                #pragma unroll
                for (int cc = 0; cc < 2; cc++) {
                    int col = wn * 64 + nt * 8 + (lane & 3) * 2 + cc;
                    float dist = fmaf(-2.0f, acc[mt][nt][half * 2 + cc], sEn[col]);
                    u64 pk = packdi(dist, n0 + col);
                    if (pk < t1) { t2 = t1; t1 = pk; }
                    else if (pk < t2) { t2 = pk; }
                }
            }
            #pragma unroll
            for (int dlt = 1; dlt <= 2; dlt <<= 1) {
                u64 o1 = __shfl_xor_sync(0xffffffffu, t1, dlt);
                u64 o2 = __shfl_xor_sync(0xffffffffu, t2, dlt);
                u64 n1 = min(t1, o1);
                u64 n2 = min(max(t1, o1), min(t2, o2));
                t1 = n1; t2 = n2;
            }
            if ((lane & 3) == 0) {
                int rl = wm * 32 + mt * 16 + half * 8 + (lane >> 2);
                sPart[rl * 4 + wn * 2] = t1;
                sPart[rl * 4 + wn * 2 + 1] = t2;
            }
        }
    }
    __syncthreads();
    if (tid < 128) {
        u64 a1 = sPart[tid * 4], a2 = sPart[tid * 4 + 1];
        u64 b1 = sPart[tid * 4 + 2], b2 = sPart[tid * 4 + 3];
        u64 n1 = min(a1, b1);
        u64 n2 = min(max(a1, b1), min(a2, b2));
        g_part[(size_t)(m0 + tid) * 128 + ntile * 2] = n1;
        g_part[(size_t)(m0 + tid) * 128 + ntile * 2 + 1] = n2;
    }
}

// ---------------- merge_fast: warp/row, fast path or enqueue candidate tasks --------
__global__ void merge_fast_kernel(float* __restrict__ out) {
    int wid = threadIdx.x >> 5, lane = threadIdx.x & 31;
    int row = blockIdx.x * 8 + wid;

    const ulonglong2* pp = (const ulonglong2*)(g_part + (size_t)row * 128);
    ulonglong2 ea = pp[lane * 2], eb = pp[lane * 2 + 1];

    u64 m = min(min(ea.x, ea.y), min(eb.x, eb.y));
    #pragma unroll
    for (int o = 16; o > 0; o >>= 1) m = min(m, __shfl_xor_sync(0xffffffffu, m, o));

    float pad = 0.00196f * sqrtf(__ldg(&g_xn2[row]) * __int_as_float(g_maxen)) + 0.05f;
    float thr = unpackd(m) + pad;

    bool f0 = unpackd(ea.y) <= thr;               // tile 2*lane needs full recheck
    bool f1 = unpackd(eb.y) <= thr;               // tile 2*lane+1
    bool c0 = (!f0) && (unpackd(ea.x) <= thr);
    bool c1 = (!f1) && (unpackd(eb.x) <= thr);
    unsigned mf = __ballot_sync(0xffffffffu, f0 | f1);
    int nc = (int)c0 + (int)c1;
    #pragma unroll
    for (int o = 16; o > 0; o >>= 1) nc += __shfl_xor_sync(0xffffffffu, nc, o);

    if (mf == 0 && nc == 1) {
        if (lane == 0) {
            int k = (int)(m & 0xFFFFFFFFu);
            g_idx[row] = k;
            out[IDX_OFF + row] = (float)k;
        }
        return;
    }

    // slow path: register row, init best, enqueue per-candidate tasks
    if (lane == 0) {
        g_best[row] = ~0ull;
        g_rowq[atomicAdd(&g_rqn, 1)] = row;
    }
    int rsh = row << 13;
    if (c0) {
        int q = atomicAdd(&g_qn, 1);
        if (q < QCAP) g_queue[q] = rsh | (int)(ea.x & 0x1FFFu);
    }
    if (c1) {
        int q = atomicAdd(&g_qn, 1);
        if (q < QCAP) g_queue[q] = rsh | (int)(eb.x & 0x1FFFu);
    }
    if (f0) {
        int q = atomicAdd(&g_qn, 128);
        int k0 = (lane * 2) * 128;
        for (int i = 0; i < 128 && q + i < QCAP; i++) g_queue[q + i] = rsh | (k0 + i);
    }
    if (f1) {
        int q = atomicAdd(&g_qn, 128);
        int k0 = (lane * 2 + 1) * 128;
        for (int i = 0; i < 128 && q + i < QCAP; i++) g_queue[q + i] = rsh | (k0 + i);
    }
}

// ---------------- merge_slow: one warp per candidate task ---------------------------
__global__ void __launch_bounds__(256, 8)
merge_slow_kernel(const float* __restrict__ E) {
    int nt = g_qn;
    if (nt > QCAP) nt = QCAP;
    int lane = threadIdx.x & 31;
    int gw = (blockIdx.x * 256 + threadIdx.x) >> 5;
    int nwarp = (gridDim.x * 256) >> 5;

    for (int t = gw; t < nt; t += nwarp) {
        int task = g_queue[t];
        int row = task >> 13, k = task & 0x1FFF;
        const float* xr = g_Axf + (size_t)row * D;
        const float* ek = E + (size_t)k * D;
        float s = 0.0f;
        #pragma unroll
        for (int j = 0; j < 8; j++)
            s = fmaf(__ldg(xr + lane + j * 32), __ldg(ek + lane + j * 32), s);
        #pragma unroll
        for (int o = 16; o > 0; o >>= 1) s += __shfl_xor_sync(0xffffffffu, s, o);
        if (lane == 0) {
            float dist = fmaf(-2.0f, s, __ldg(&g_en2[k]));
            atomicMin(&g_best[row], packdi(dist, k));
        }
    }
}

// ---------------- merge_fin: finalize queued rows ------------------------------------
__global__ void merge_fin_kernel(float* __restrict__ out) {
    int n = g_rqn;
    for (int i = blockIdx.x * 256 + threadIdx.x; i < n; i += gridDim.x * 256) {
        int row = g_rowq[i];
        int k = (int)(g_best[row] & 0xFFFFFFFFu);
        g_idx[row] = k;
        out[IDX_OFF + row] = (float)k;
    }
}

// ---------------- final gather + loss (float4) --------------------------------------
__global__ void final_kernel(const float* __restrict__ hs,
                             const float* __restrict__ E,
                             float* __restrict__ out) {
    __shared__ int sIdx[128];
    __shared__ float sRed[8];
    int tid = threadIdx.x;
    int lane = tid & 31;
    int row0 = blockIdx.x * 128;
    int b = row0 >> 10, p0 = row0 & 1023;
    size_t xbase = (size_t)b * 256 * 1024 + p0;

    if (tid < 128) sIdx[tid] = g_idx[row0 + tid];
    __syncthreads();

    int k0 = sIdx[lane * 4], k1 = sIdx[lane * 4 + 1];
    int k2 = sIdx[lane * 4 + 2], k3 = sIdx[lane * 4 + 3];

    float lsum = 0.0f;
    #pragma unroll 4
    for (int i = 0; i < 32; i++) {
        int c = i * 8 + (tid >> 5);
        size_t ad = xbase + (size_t)c * 1024 + lane * 4;
        float4 xv = *(const float4*)(hs + ad);
        float4 ev;
        ev.x = __ldg(E + (size_t)k0 * D + c);
        ev.y = __ldg(E + (size_t)k1 * D + c);
        ev.z = __ldg(E + (size_t)k2 * D + c);
        ev.w = __ldg(E + (size_t)k3 * D + c);
        *(float4*)(out + ad) = ev;
        float d0 = ev.x - xv.x, d1 = ev.y - xv.y;
        float d2 = ev.z - xv.z, d3 = ev.w - xv.w;
        lsum = fmaf(d0, d0, lsum);
        lsum = fmaf(d1, d1, lsum);
        lsum = fmaf(d2, d2, lsum);
        lsum = fmaf(d3, d3, lsum);
    }
    #pragma unroll
    for (int o = 16; o > 0; o >>= 1) lsum += __shfl_xor_sync(0xffffffffu, lsum, o);
    if ((tid & 31) == 0) sRed[tid >> 5] = lsum;
    __syncthreads();
    if (tid == 0) {
        float tot = 0.0f;
        #pragma unroll
        for (int w = 0; w < 8; w++) tot += sRed[w];
        atomicAdd(out + LOSS_OFF, tot * (1.25f / 4194304.0f));
    }
}

extern "C" void kernel_launch(void* const* d_in, const int* in_sizes, int n_in,
                              void* d_out, int out_size) {
    const float* hs = (const float*)d_in[0];
    const float* E  = (const float*)d_in[1];
    float* out = (float*)d_out;

    cudaFuncSetAttribute(gemm_kernel,
                         cudaFuncAttributeMaxDynamicSharedMemorySize, SMEM_SZ);

    prepE_kernel<<<KC / 8, 256>>>(E, out);
    prepA_kernel<<<N_ROWS / 32, dim3(32, 8)>>>(hs);
    gemm_kernel<<<dim3(KC / 128, N_ROWS / 128), 256, SMEM_SZ>>>();
    merge_fast_kernel<<<N_ROWS / 8, 256>>>(out);
    merge_slow_kernel<<<592, 256>>>(E);
    merge_fin_kernel<<<32, 256>>>(out);
    final_kernel<<<N_ROWS / 128, 256>>>(hs, E, out);
}